// round 14
// baseline (speedup 1.0000x reference)
#include <cuda_runtime.h>
#include <cuda_fp16.h>
#include <cstdint>

// Problem constants
#define BATCH 4096
#define DIM   768
#define FEAT  16384
#define TOPK  64

// operand pre-scaling (keeps fp16 split residuals in normal range)
#define XSCALE 16.0f
#define WSCALE 64.0f
#define UNSCALE (1.0f / (XSCALE * WSCALE))

// GEMM tile config: CTA 256x128, 8 warps (4x2), warp tile 64x64, BK=32 (fp16)
#define BM 256
#define BN 128
#define BK 32
#define NSTAGE 3
#define GTHREADS 256
#define NCHUNK (DIM / BK)          // 24
#define RS 40                      // smem row stride in halves (80B) - ldmatrix conflict-free
// stage layout (offsets in halves)
#define OFF_AH 0
#define OFF_AL (BM * RS)                  // 10240
#define OFF_BH (2 * BM * RS)              // 20480
#define OFF_BL (2 * BM * RS + BN * RS)    // 25600
#define STAGE_HALVES (2 * BM * RS + 2 * BN * RS)  // 30720
#define STAGE_BYTES (STAGE_HALVES * 2)            // 61440
#define SMEM_BYTES (NSTAGE * STAGE_BYTES)         // 184320

// topk smem: keys[FEAT] + hist[2048]
#define TK_SMEM_BYTES ((FEAT + 2048) * 4)         // 73728

// ---------------- scratch (device globals; no allocation allowed) ----------
__device__ float g_pre[(size_t)BATCH * FEAT];             // pre-activations (256 MB)
__device__ float g_WdT[(size_t)FEAT * DIM];               // W_dec transposed (50 MB)
__device__ int   g_tidx[BATCH * TOPK];
__device__ float g_tval[BATCH * TOPK];
// fp16 hi/lo splits of scaled operands
__device__ __half g_xh[BATCH * DIM];
__device__ __half g_xl[BATCH * DIM];
__device__ __half g_wh[(size_t)FEAT * DIM];
__device__ __half g_wl[(size_t)FEAT * DIM];

// ---------------- helpers ---------------------------------------------------
__device__ __forceinline__ uint32_t smem_u32(const void* p) {
    uint32_t a;
    asm("{ .reg .u64 t; cvta.to.shared.u64 t, %1; cvt.u32.u64 %0, t; }" : "=r"(a) : "l"(p));
    return a;
}
__device__ __forceinline__ void split_fp16(float v, __half& hi, __half& lo) {
    __half h = __float2half_rn(v);
    float r = v - __half2float(h);      // exact in fp32
    hi = h;
    lo = __float2half_rn(r);
}
__device__ __forceinline__ void mma_fp16(float* c, const uint32_t* a, uint32_t b0, uint32_t b1) {
    asm volatile(
        "mma.sync.aligned.m16n8k16.row.col.f32.f16.f16.f32 "
        "{%0,%1,%2,%3}, {%4,%5,%6,%7}, {%8,%9}, {%0,%1,%2,%3};\n"
        : "+f"(c[0]), "+f"(c[1]), "+f"(c[2]), "+f"(c[3])
        : "r"(a[0]), "r"(a[1]), "r"(a[2]), "r"(a[3]), "r"(b0), "r"(b1));
}
#define LDMATRIX_X4(r0, r1, r2, r3, addr) \
    asm volatile("ldmatrix.sync.aligned.m8n8.x4.shared.b16 {%0,%1,%2,%3}, [%4];" \
                 : "=r"(r0), "=r"(r1), "=r"(r2), "=r"(r3) : "r"(addr))
#define CP_ASYNC16(dst, src) \
    asm volatile("cp.async.cg.shared.global [%0], [%1], 16;" :: "r"(dst), "l"(src))
#define CP_COMMIT() asm volatile("cp.async.commit_group;" ::: "memory")
#define CP_WAIT(n)  asm volatile("cp.async.wait_group %0;" :: "n"(n) : "memory")

// ---------------- kernel: fused fp16 splits (x then W, one launch) -----------
__global__ void __launch_bounds__(256) split_xw_kernel(const float* __restrict__ x,
                                                       const float* __restrict__ b_dec,
                                                       const float* __restrict__ W) {
    size_t i = (size_t)blockIdx.x * 256 + threadIdx.x;
    const size_t NX = (size_t)BATCH * DIM;
    if (i < NX) {
        float a = (x[i] - b_dec[i % DIM]) * XSCALE;
        __half h, l;
        split_fp16(a, h, l);
        g_xh[i] = h; g_xl[i] = l;
    }
    // W work: same grid covers FEAT*DIM with a second index space
    size_t j = i;
    const size_t NW = (size_t)FEAT * DIM;
    // grid sized for NW (> NX); every thread does one W element
    if (j < NW) {
        __half h, l;
        split_fp16(W[j] * WSCALE, h, l);
        g_wh[j] = h; g_wl[j] = l;
    }
}

// ---------------- kernel: transpose W_dec [D,F] -> [F,D] ---------------------
__global__ void transpose_wdec_kernel(const float* __restrict__ Wd) {
    __shared__ float tile[32][33];
    int f0 = blockIdx.x * 32;
    int d0 = blockIdx.y * 32;
    int tx = threadIdx.x, ty = threadIdx.y;   // block (32, 8)
    #pragma unroll
    for (int i = 0; i < 32; i += 8)
        tile[ty + i][tx] = Wd[(size_t)(d0 + ty + i) * FEAT + f0 + tx];
    __syncthreads();
    #pragma unroll
    for (int i = 0; i < 32; i += 8)
        g_WdT[(size_t)(f0 + ty + i) * DIM + d0 + tx] = tile[tx][ty + i];
}

// ---------------- kernel: encode GEMM, 2-split fp16 (hh+hl+lh) ---------------
// g_pre[m,n] = (sum_k xs[m,k]*ws[n,k]) / 1024 + b_enc[n]
__device__ __forceinline__ void load_stage(uint32_t sbase, int chunk, int m0, int n0, int tid) {
    const int k0 = chunk * BK;
    #pragma unroll
    for (int p = 0; p < 12; p++) {
        int s = tid + p * GTHREADS;          // 0..3071
        if (s < 1024) {                      // A_hi: 256 rows x 4 segs of 8 halves
            int r = s >> 2, q = s & 3;
            CP_ASYNC16(sbase + (OFF_AH + r * RS + q * 8) * 2,
                       g_xh + (size_t)(m0 + r) * DIM + k0 + q * 8);
        } else if (s < 2048) {               // A_lo
            int s2 = s - 1024;
            int r = s2 >> 2, q = s2 & 3;
            CP_ASYNC16(sbase + (OFF_AL + r * RS + q * 8) * 2,
                       g_xl + (size_t)(m0 + r) * DIM + k0 + q * 8);
        } else if (s < 2560) {               // B_hi: 128 rows x 4 segs
            int s2 = s - 2048;
            int r = s2 >> 2, q = s2 & 3;
            CP_ASYNC16(sbase + (OFF_BH + r * RS + q * 8) * 2,
                       g_wh + (size_t)(n0 + r) * DIM + k0 + q * 8);
        } else {                             // B_lo
            int s2 = s - 2560;
            int r = s2 >> 2, q = s2 & 3;
            CP_ASYNC16(sbase + (OFF_BL + r * RS + q * 8) * 2,
                       g_wl + (size_t)(n0 + r) * DIM + k0 + q * 8);
        }
    }
}

__global__ void __launch_bounds__(GTHREADS, 1) encode_gemm_kernel(
    const float* __restrict__ bias) {
    extern __shared__ __align__(16) char smem[];
    const int tid = threadIdx.x;
    const int lane = tid & 31;
    const int wid = tid >> 5;
    const int warp_m = wid >> 1;     // 0..3 -> 64-row slab
    const int warp_n = wid & 1;      // 0..1 -> 64-col slab
    const int m0 = blockIdx.x * BM;  // x = M: wave working set fits L2
    const int n0 = blockIdx.y * BN;
    const uint32_t smem_base = smem_u32(smem);

    // ldmatrix lane-address components (halves offsets within a stage)
    const int aRow = warp_m * 64 + (lane & 7) + ((lane >> 3) & 1) * 8;
    const int aK   = ((lane >> 4) & 1) * 8;
    const int bRow = warp_n * 64 + (lane & 7) + ((lane >> 4) & 1) * 8;
    const int bK   = ((lane >> 3) & 1) * 8;

    const uint32_t aOffH = (uint32_t)(OFF_AH + aRow * RS + aK) * 2;
    const uint32_t aOffL = (uint32_t)(OFF_AL + aRow * RS + aK) * 2;
    const uint32_t bOffH = (uint32_t)(OFF_BH + bRow * RS + bK) * 2;
    const uint32_t bOffL = (uint32_t)(OFF_BL + bRow * RS + bK) * 2;

    float acc[4][8][4];
    #pragma unroll
    for (int i = 0; i < 4; i++)
        #pragma unroll
        for (int j = 0; j < 8; j++)
            #pragma unroll
            for (int r = 0; r < 4; r++) acc[i][j][r] = 0.f;

    // prologue: prefetch 2 stages
    load_stage(smem_base, 0, m0, n0, tid);
    CP_COMMIT();
    load_stage(smem_base + STAGE_BYTES, 1, m0, n0, tid);
    CP_COMMIT();

    for (int chunk = 0; chunk < NCHUNK; chunk++) {
        CP_WAIT(1);              // chunk's data has arrived (chunk+1 may still fly)
        __syncthreads();         // release compute AND protect buffer (chunk-1)%3

        // issue chunk+2 into buffer (chunk+2)%3 == (chunk-1)%3 (readers all passed barrier)
        int next = chunk + 2;
        if (next < NCHUNK)
            load_stage(smem_base + (next % NSTAGE) * STAGE_BYTES, next, m0, n0, tid);
        CP_COMMIT();             // unconditional: keeps group-count semantics

        const uint32_t sb = smem_base + (chunk % NSTAGE) * STAGE_BYTES;

        #pragma unroll
        for (int k16 = 0; k16 < 2; k16++) {
            const uint32_t kb2 = (uint32_t)(k16 * 16) * 2;   // byte offset of k base

            // ---- hoist ALL fragment loads, then one uninterrupted MMA stream ----
            uint32_t Ah[4][4], Al[4][4], Bh[4][4], Bl[4][4];
            #pragma unroll
            for (int mt = 0; mt < 4; mt++)
                LDMATRIX_X4(Ah[mt][0], Ah[mt][1], Ah[mt][2], Ah[mt][3],
                            sb + aOffH + (uint32_t)(mt * 16 * RS) * 2 + kb2);
            #pragma unroll
            for (int pr = 0; pr < 4; pr++)
                LDMATRIX_X4(Bh[pr][0], Bh[pr][1], Bh[pr][2], Bh[pr][3],
                            sb + bOffH + (uint32_t)(pr * 16 * RS) * 2 + kb2);
            #pragma unroll
            for (int pr = 0; pr < 4; pr++)
                LDMATRIX_X4(Bl[pr][0], Bl[pr][1], Bl[pr][2], Bl[pr][3],
                            sb + bOffL + (uint32_t)(pr * 16 * RS) * 2 + kb2);
            #pragma unroll
            for (int mt = 0; mt < 4; mt++)
                LDMATRIX_X4(Al[mt][0], Al[mt][1], Al[mt][2], Al[mt][3],
                            sb + aOffL + (uint32_t)(mt * 16 * RS) * 2 + kb2);

            #pragma unroll
            for (int mt = 0; mt < 4; mt++)
                #pragma unroll
                for (int nt = 0; nt < 8; nt++)
                    mma_fp16(acc[mt][nt], Ah[mt], Bh[nt >> 1][(nt & 1) * 2],
                             Bh[nt >> 1][(nt & 1) * 2 + 1]);
            #pragma unroll
            for (int mt = 0; mt < 4; mt++)
                #pragma unroll
                for (int nt = 0; nt < 8; nt++)
                    mma_fp16(acc[mt][nt], Ah[mt], Bl[nt >> 1][(nt & 1) * 2],
                             Bl[nt >> 1][(nt & 1) * 2 + 1]);
            #pragma unroll
            for (int mt = 0; mt < 4; mt++)
                #pragma unroll
                for (int nt = 0; nt < 8; nt++)
                    mma_fp16(acc[mt][nt], Al[mt], Bh[nt >> 1][(nt & 1) * 2],
                             Bh[nt >> 1][(nt & 1) * 2 + 1]);
        }
    }

    // epilogue: acc/1024 + bias -> g_pre
    const int lr = lane >> 2;
    const int lc = lane & 3;
    #pragma unroll
    for (int mt = 0; mt < 4; mt++) {
        #pragma unroll
        for (int nt = 0; nt < 8; nt++) {
            int row = m0 + warp_m * 64 + mt * 16 + lr;
            int col = n0 + warp_n * 64 + nt * 8 + 2 * lc;
            float2 bv = *(const float2*)&bias[col];
            float2 o0 = make_float2(acc[mt][nt][0] * UNSCALE + bv.x,
                                    acc[mt][nt][1] * UNSCALE + bv.y);
            float2 o1 = make_float2(acc[mt][nt][2] * UNSCALE + bv.x,
                                    acc[mt][nt][3] * UNSCALE + bv.y);
            *(float2*)&g_pre[(size_t)row * FEAT + col] = o0;
            *(float2*)&g_pre[(size_t)(row + 8) * FEAT + col] = o1;
        }
    }
}

// ---------------- helpers for topk ------------------------------------------
__device__ __forceinline__ unsigned fkey(float v) {
    unsigned u = __float_as_uint(v);
    return (u & 0x80000000u) ? ~u : (u | 0x80000000u);
}
__device__ __forceinline__ float key_to_float(unsigned k) {
    unsigned u = (k & 0x80000000u) ? (k & 0x7fffffffu) : ~k;
    return __uint_as_float(u);
}

// ---------------- kernel: exact top-64 per row (radix select, smem-cached) ---
__global__ void __launch_bounds__(256) topk_kernel() {
    extern __shared__ uint32_t tk[];        // keys[FEAT] then hist[2048]
    uint32_t* keys = tk;
    uint32_t* hist = tk + FEAT;

    const int row = blockIdx.x;
    const int tid = threadIdx.x;

    __shared__ unsigned tsum[256];
    __shared__ unsigned sh_digit, sh_need;
    __shared__ int cnt, eqn;
    __shared__ int eqbuf[256];

    for (int i = tid; i < 2048; i += 256) hist[i] = 0;
    __syncthreads();

    const float4* p4 = (const float4*)(g_pre + (size_t)row * FEAT);
    #pragma unroll
    for (int it = 0; it < 16; it++) {
        int i = tid + it * 256;
        float4 v = p4[i];
        unsigned k0 = fkey(v.x), k1 = fkey(v.y), k2 = fkey(v.z), k3 = fkey(v.w);
        keys[i * 4 + 0] = k0; keys[i * 4 + 1] = k1;
        keys[i * 4 + 2] = k2; keys[i * 4 + 3] = k3;
        atomicAdd(&hist[k0 >> 21], 1u);
        atomicAdd(&hist[k1 >> 21], 1u);
        atomicAdd(&hist[k2 >> 21], 1u);
        atomicAdd(&hist[k3 >> 21], 1u);
    }
    __syncthreads();

    unsigned prefix = 0;
    unsigned need = TOPK;
    const int shifts[3]  = {21, 10, 0};
    const int bitsArr[3] = {11, 11, 10};

    for (int lvl = 0; lvl < 3; lvl++) {
        const int shift = shifts[lvl];
        const int bits = bitsArr[lvl];
        const int nb = 1 << bits;

        if (lvl > 0) {
            for (int i = tid; i < nb; i += 256) hist[i] = 0;
            __syncthreads();
            for (int it = 0; it < FEAT / 256; it++) {
                unsigned key = keys[tid + it * 256];
                if ((key >> (shift + bits)) == prefix)
                    atomicAdd(&hist[(key >> shift) & (nb - 1)], 1u);
            }
            __syncthreads();
        }

        const int stride = nb / 256;
        unsigned s = 0;
        #pragma unroll 4
        for (int j = 0; j < stride; j++) s += hist[tid * stride + j];
        tsum[tid] = s;
        __syncthreads();
        if (tid == 0) {
            unsigned cum = 0;
            int t = 255;
            for (; t >= 0; t--) {
                if (cum + tsum[t] >= need) break;
                cum += tsum[t];
            }
            unsigned dig = 0;
            for (int b = (t + 1) * stride - 1; b >= t * stride; b--) {
                unsigned h = hist[b];
                if (cum + h >= need) { dig = (unsigned)b; break; }
                cum += h;
            }
            sh_digit = dig;
            sh_need = need - cum;
        }
        __syncthreads();
        prefix = (prefix << bits) | sh_digit;
        need = sh_need;
        __syncthreads();
    }

    const unsigned T = prefix;
    if (tid == 0) { cnt = 0; eqn = 0; }
    __syncthreads();

    for (int it = 0; it < FEAT / 256; it++) {
        int i = tid + it * 256;
        unsigned key = keys[i];
        if (key > T) {
            int s2 = atomicAdd(&cnt, 1);
            g_tidx[row * TOPK + s2] = i;
            g_tval[row * TOPK + s2] = key_to_float(key);
        } else if (key == T) {
            int e = atomicAdd(&eqn, 1);
            if (e < 256) eqbuf[e] = i;
        }
    }
    __syncthreads();

    if (tid == 0) {
        int ne = eqn; if (ne > 256) ne = 256;
        for (int a = 1; a < ne; a++) {
            int v = eqbuf[a]; int b = a - 1;
            while (b >= 0 && eqbuf[b] > v) { eqbuf[b + 1] = eqbuf[b]; b--; }
            eqbuf[b + 1] = v;
        }
        float tv = key_to_float(T);
        int base = cnt;
        for (int j = 0; j < (int)need; j++) {
            g_tidx[row * TOPK + base + j] = eqbuf[j];
            g_tval[row * TOPK + base + j] = tv;
        }
    }
}

// ---------------- kernel: sparse decode ---------------------------------------
__global__ void __launch_bounds__(256) decode_kernel(const float* __restrict__ b_dec,
                                                     float* __restrict__ out) {
    const int row = blockIdx.x;
    const int t = threadIdx.x;
    __shared__ int   sidx[TOPK];
    __shared__ float sval[TOPK];
    if (t < TOPK) {
        sidx[t] = g_tidx[row * TOPK + t];
        sval[t] = g_tval[row * TOPK + t];
    }
    __syncthreads();

    float a0 = b_dec[t];
    float a1 = b_dec[t + 256];
    float a2 = b_dec[t + 512];
    #pragma unroll 8
    for (int k = 0; k < TOPK; k++) {
        const float* w = g_WdT + (size_t)sidx[k] * DIM;
        float v = sval[k];
        a0 += v * w[t];
        a1 += v * w[t + 256];
        a2 += v * w[t + 512];
    }
    float* o = out + (size_t)row * DIM;
    o[t] = a0;
    o[t + 256] = a1;
    o[t + 512] = a2;
}

// ---------------- launcher -----------------------------------------------------
extern "C" void kernel_launch(void* const* d_in, const int* in_sizes, int n_in,
                              void* d_out, int out_size) {
    const float* x     = (const float*)d_in[0];
    const float* W_enc = (const float*)d_in[1];
    const float* b_enc = (const float*)d_in[2];
    const float* W_dec = (const float*)d_in[3];
    const float* b_dec = (const float*)d_in[4];
    float* out = (float*)d_out;

    cudaFuncSetAttribute(encode_gemm_kernel,
                         cudaFuncAttributeMaxDynamicSharedMemorySize, SMEM_BYTES);
    cudaFuncSetAttribute(topk_kernel,
                         cudaFuncAttributeMaxDynamicSharedMemorySize, TK_SMEM_BYTES);

    split_xw_kernel<<<(int)(((size_t)FEAT * DIM + 255) / 256), 256>>>(x, b_dec, W_enc);

    dim3 tgrid(FEAT / 32, DIM / 32);
    dim3 tblk(32, 8);
    transpose_wdec_kernel<<<tgrid, tblk>>>(W_dec);

    dim3 ggrid(BATCH / BM, FEAT / BN);   // x = M tiles, y = N tiles
    encode_gemm_kernel<<<ggrid, GTHREADS, SMEM_BYTES>>>(b_enc);

    topk_kernel<<<BATCH, 256, TK_SMEM_BYTES>>>();

    decode_kernel<<<BATCH, 256>>>(b_dec, out);
}

// round 15
// speedup vs baseline: 1.6031x; 1.6031x over previous
#include <cuda_runtime.h>
#include <cuda_fp16.h>
#include <cstdint>

// Problem constants
#define BATCH 4096
#define DIM   768
#define FEAT  16384
#define TOPK  64

// operand pre-scaling (keeps fp16 split residuals in normal range)
#define XSCALE 16.0f
#define WSCALE 64.0f
#define UNSCALE (1.0f / (XSCALE * WSCALE))

// GEMM tile config: CTA 256x128, 8 warps (4x2), warp tile 64x64, BK=32 (fp16)
#define BM 256
#define BN 128
#define BK 32
#define NSTAGE 3
#define GTHREADS 256
#define NCHUNK (DIM / BK)          // 24
#define RS 40                      // smem row stride in halves (80B) - ldmatrix conflict-free
// stage layout (offsets in halves)
#define OFF_AH 0
#define OFF_AL (BM * RS)                  // 10240
#define OFF_BH (2 * BM * RS)              // 20480
#define OFF_BL (2 * BM * RS + BN * RS)    // 25600
#define STAGE_HALVES (2 * BM * RS + 2 * BN * RS)  // 30720
#define STAGE_BYTES (STAGE_HALVES * 2)            // 61440
#define SMEM_BYTES (NSTAGE * STAGE_BYTES)         // 184320

// topk smem: keys[FEAT] + hist[2048]
#define TK_SMEM_BYTES ((FEAT + 2048) * 4)         // 73728

// ---------------- scratch (device globals; no allocation allowed) ----------
__device__ float g_pre[(size_t)BATCH * FEAT];             // pre-activations (256 MB)
__device__ float g_WdT[(size_t)FEAT * DIM];               // W_dec transposed (50 MB)
__device__ int   g_tidx[BATCH * TOPK];
__device__ float g_tval[BATCH * TOPK];
// fp16 hi/lo splits of scaled operands
__device__ __half g_xh[BATCH * DIM];
__device__ __half g_xl[BATCH * DIM];
__device__ __half g_wh[(size_t)FEAT * DIM];
__device__ __half g_wl[(size_t)FEAT * DIM];

// ---------------- helpers ---------------------------------------------------
__device__ __forceinline__ uint32_t smem_u32(const void* p) {
    uint32_t a;
    asm("{ .reg .u64 t; cvta.to.shared.u64 t, %1; cvt.u32.u64 %0, t; }" : "=r"(a) : "l"(p));
    return a;
}
__device__ __forceinline__ void split_fp16(float v, __half& hi, __half& lo) {
    __half h = __float2half_rn(v);
    float r = v - __half2float(h);      // exact in fp32
    hi = h;
    lo = __float2half_rn(r);
}
__device__ __forceinline__ void mma_fp16(float* c, const uint32_t* a, uint32_t b0, uint32_t b1) {
    asm volatile(
        "mma.sync.aligned.m16n8k16.row.col.f32.f16.f16.f32 "
        "{%0,%1,%2,%3}, {%4,%5,%6,%7}, {%8,%9}, {%0,%1,%2,%3};\n"
        : "+f"(c[0]), "+f"(c[1]), "+f"(c[2]), "+f"(c[3])
        : "r"(a[0]), "r"(a[1]), "r"(a[2]), "r"(a[3]), "r"(b0), "r"(b1));
}
#define LDMATRIX_X4(r0, r1, r2, r3, addr) \
    asm volatile("ldmatrix.sync.aligned.m8n8.x4.shared.b16 {%0,%1,%2,%3}, [%4];" \
                 : "=r"(r0), "=r"(r1), "=r"(r2), "=r"(r3) : "r"(addr))
#define CP_ASYNC16(dst, src) \
    asm volatile("cp.async.cg.shared.global [%0], [%1], 16;" :: "r"(dst), "l"(src))
#define CP_COMMIT() asm volatile("cp.async.commit_group;" ::: "memory")
#define CP_WAIT(n)  asm volatile("cp.async.wait_group %0;" :: "n"(n) : "memory")

// ---------------- kernel: fused fp16 splits (x and W, one launch) ------------
__global__ void __launch_bounds__(256) split_xw_kernel(const float* __restrict__ x,
                                                       const float* __restrict__ b_dec,
                                                       const float* __restrict__ W) {
    size_t i = (size_t)blockIdx.x * 256 + threadIdx.x;
    const size_t NX = (size_t)BATCH * DIM;
    if (i < NX) {
        float a = (x[i] - b_dec[i % DIM]) * XSCALE;
        __half h, l;
        split_fp16(a, h, l);
        g_xh[i] = h; g_xl[i] = l;
    }
    const size_t NW = (size_t)FEAT * DIM;
    if (i < NW) {
        __half h, l;
        split_fp16(W[i] * WSCALE, h, l);
        g_wh[i] = h; g_wl[i] = l;
    }
}

// ---------------- kernel: transpose W_dec [D,F] -> [F,D] ---------------------
__global__ void transpose_wdec_kernel(const float* __restrict__ Wd) {
    __shared__ float tile[32][33];
    int f0 = blockIdx.x * 32;
    int d0 = blockIdx.y * 32;
    int tx = threadIdx.x, ty = threadIdx.y;   // block (32, 8)
    #pragma unroll
    for (int i = 0; i < 32; i += 8)
        tile[ty + i][tx] = Wd[(size_t)(d0 + ty + i) * FEAT + f0 + tx];
    __syncthreads();
    #pragma unroll
    for (int i = 0; i < 32; i += 8)
        g_WdT[(size_t)(f0 + ty + i) * DIM + d0 + tx] = tile[tx][ty + i];
}

// ---------------- kernel: encode GEMM, 2-split fp16 (hh+hl+lh) ---------------
// g_pre[m,n] = (sum_k xs[m,k]*ws[n,k]) / 1024 + b_enc[n]
__device__ __forceinline__ void load_stage(uint32_t sbase, int chunk, int m0, int n0, int tid) {
    const int k0 = chunk * BK;
    #pragma unroll
    for (int p = 0; p < 12; p++) {
        int s = tid + p * GTHREADS;          // 0..3071
        if (s < 1024) {                      // A_hi: 256 rows x 4 segs of 8 halves
            int r = s >> 2, q = s & 3;
            CP_ASYNC16(sbase + (OFF_AH + r * RS + q * 8) * 2,
                       g_xh + (size_t)(m0 + r) * DIM + k0 + q * 8);
        } else if (s < 2048) {               // A_lo
            int s2 = s - 1024;
            int r = s2 >> 2, q = s2 & 3;
            CP_ASYNC16(sbase + (OFF_AL + r * RS + q * 8) * 2,
                       g_xl + (size_t)(m0 + r) * DIM + k0 + q * 8);
        } else if (s < 2560) {               // B_hi: 128 rows x 4 segs
            int s2 = s - 2048;
            int r = s2 >> 2, q = s2 & 3;
            CP_ASYNC16(sbase + (OFF_BH + r * RS + q * 8) * 2,
                       g_wh + (size_t)(n0 + r) * DIM + k0 + q * 8);
        } else {                             // B_lo
            int s2 = s - 2560;
            int r = s2 >> 2, q = s2 & 3;
            CP_ASYNC16(sbase + (OFF_BL + r * RS + q * 8) * 2,
                       g_wl + (size_t)(n0 + r) * DIM + k0 + q * 8);
        }
    }
}

__global__ void __launch_bounds__(GTHREADS, 1) encode_gemm_kernel(
    const float* __restrict__ bias) {
    extern __shared__ __align__(16) char smem[];
    const int tid = threadIdx.x;
    const int lane = tid & 31;
    const int wid = tid >> 5;
    const int warp_m = wid >> 1;     // 0..3 -> 64-row slab
    const int warp_n = wid & 1;      // 0..1 -> 64-col slab
    const int m0 = blockIdx.x * BM;  // x = M: wave working set fits L2
    const int n0 = blockIdx.y * BN;
    const uint32_t smem_base = smem_u32(smem);

    // ldmatrix lane-address components (halves offsets within a stage)
    const int aRow = warp_m * 64 + (lane & 7) + ((lane >> 3) & 1) * 8;
    const int aK   = ((lane >> 4) & 1) * 8;
    const int bRow = warp_n * 64 + (lane & 7) + ((lane >> 4) & 1) * 8;
    const int bK   = ((lane >> 3) & 1) * 8;

    const uint32_t aOffH = (uint32_t)(OFF_AH + aRow * RS + aK) * 2;
    const uint32_t aOffL = (uint32_t)(OFF_AL + aRow * RS + aK) * 2;
    const uint32_t bOffH = (uint32_t)(OFF_BH + bRow * RS + bK) * 2;
    const uint32_t bOffL = (uint32_t)(OFF_BL + bRow * RS + bK) * 2;

    float acc[4][8][4];
    #pragma unroll
    for (int i = 0; i < 4; i++)
        #pragma unroll
        for (int j = 0; j < 8; j++)
            #pragma unroll
            for (int r = 0; r < 4; r++) acc[i][j][r] = 0.f;

    // prologue: prefetch 2 stages
    load_stage(smem_base, 0, m0, n0, tid);
    CP_COMMIT();
    load_stage(smem_base + STAGE_BYTES, 1, m0, n0, tid);
    CP_COMMIT();

    for (int chunk = 0; chunk < NCHUNK; chunk++) {
        CP_WAIT(1);              // chunk's data has arrived (chunk+1 may still fly)
        __syncthreads();         // release compute AND protect buffer (chunk-1)%3

        // issue chunk+2 into buffer (chunk+2)%3 == (chunk-1)%3 (readers all passed barrier)
        int next = chunk + 2;
        if (next < NCHUNK)
            load_stage(smem_base + (next % NSTAGE) * STAGE_BYTES, next, m0, n0, tid);
        CP_COMMIT();             // unconditional: keeps group-count semantics

        const uint32_t sb = smem_base + (chunk % NSTAGE) * STAGE_BYTES;

        #pragma unroll
        for (int k16 = 0; k16 < 2; k16++) {
            const uint32_t kb2 = (uint32_t)(k16 * 16) * 2;   // byte offset of k base

            uint32_t Ah[4][4];
            #pragma unroll
            for (int mt = 0; mt < 4; mt++)
                LDMATRIX_X4(Ah[mt][0], Ah[mt][1], Ah[mt][2], Ah[mt][3],
                            sb + aOffH + (uint32_t)(mt * 16 * RS) * 2 + kb2);
            uint32_t Bh[4][4];
            #pragma unroll
            for (int pr = 0; pr < 4; pr++)
                LDMATRIX_X4(Bh[pr][0], Bh[pr][1], Bh[pr][2], Bh[pr][3],
                            sb + bOffH + (uint32_t)(pr * 16 * RS) * 2 + kb2);
            // hh
            #pragma unroll
            for (int mt = 0; mt < 4; mt++)
                #pragma unroll
                for (int nt = 0; nt < 8; nt++)
                    mma_fp16(acc[mt][nt], Ah[mt], Bh[nt >> 1][(nt & 1) * 2],
                             Bh[nt >> 1][(nt & 1) * 2 + 1]);
            // hl: Ah x Bl
            uint32_t Bl[4][4];
            #pragma unroll
            for (int pr = 0; pr < 4; pr++)
                LDMATRIX_X4(Bl[pr][0], Bl[pr][1], Bl[pr][2], Bl[pr][3],
                            sb + bOffL + (uint32_t)(pr * 16 * RS) * 2 + kb2);
            #pragma unroll
            for (int mt = 0; mt < 4; mt++)
                #pragma unroll
                for (int nt = 0; nt < 8; nt++)
                    mma_fp16(acc[mt][nt], Ah[mt], Bl[nt >> 1][(nt & 1) * 2],
                             Bl[nt >> 1][(nt & 1) * 2 + 1]);
            // lh: Al x Bh
            uint32_t Al[4][4];
            #pragma unroll
            for (int mt = 0; mt < 4; mt++)
                LDMATRIX_X4(Al[mt][0], Al[mt][1], Al[mt][2], Al[mt][3],
                            sb + aOffL + (uint32_t)(mt * 16 * RS) * 2 + kb2);
            #pragma unroll
            for (int mt = 0; mt < 4; mt++)
                #pragma unroll
                for (int nt = 0; nt < 8; nt++)
                    mma_fp16(acc[mt][nt], Al[mt], Bh[nt >> 1][(nt & 1) * 2],
                             Bh[nt >> 1][(nt & 1) * 2 + 1]);
        }
    }

    // epilogue: acc/1024 + bias -> g_pre
    const int lr = lane >> 2;
    const int lc = lane & 3;
    #pragma unroll
    for (int mt = 0; mt < 4; mt++) {
        #pragma unroll
        for (int nt = 0; nt < 8; nt++) {
            int row = m0 + warp_m * 64 + mt * 16 + lr;
            int col = n0 + warp_n * 64 + nt * 8 + 2 * lc;
            float2 bv = *(const float2*)&bias[col];
            float2 o0 = make_float2(acc[mt][nt][0] * UNSCALE + bv.x,
                                    acc[mt][nt][1] * UNSCALE + bv.y);
            float2 o1 = make_float2(acc[mt][nt][2] * UNSCALE + bv.x,
                                    acc[mt][nt][3] * UNSCALE + bv.y);
            *(float2*)&g_pre[(size_t)row * FEAT + col] = o0;
            *(float2*)&g_pre[(size_t)(row + 8) * FEAT + col] = o1;
        }
    }
}

// ---------------- helpers for topk ------------------------------------------
__device__ __forceinline__ unsigned fkey(float v) {
    unsigned u = __float_as_uint(v);
    return (u & 0x80000000u) ? ~u : (u | 0x80000000u);
}
__device__ __forceinline__ float key_to_float(unsigned k) {
    unsigned u = (k & 0x80000000u) ? (k & 0x7fffffffu) : ~k;
    return __uint_as_float(u);
}

// ---------------- kernel: exact top-64 per row (radix select, parallel digit pick)
__global__ void __launch_bounds__(256) topk_kernel() {
    extern __shared__ uint32_t tk[];        // keys[FEAT] then hist[2048]
    uint32_t* keys = tk;
    uint32_t* hist = tk + FEAT;

    const int row = blockIdx.x;
    const int tid = threadIdx.x;

    __shared__ unsigned tsum[256];
    __shared__ unsigned sh_digit, sh_need;
    __shared__ int cnt, eqn;
    __shared__ int eqbuf[256];

    for (int i = tid; i < 2048; i += 256) hist[i] = 0;
    __syncthreads();

    // single global read: build keys + level-0 histogram (bits 31..21)
    const float4* p4 = (const float4*)(g_pre + (size_t)row * FEAT);
    #pragma unroll
    for (int it = 0; it < 16; it++) {
        int i = tid + it * 256;
        float4 v = p4[i];
        unsigned k0 = fkey(v.x), k1 = fkey(v.y), k2 = fkey(v.z), k3 = fkey(v.w);
        keys[i * 4 + 0] = k0; keys[i * 4 + 1] = k1;
        keys[i * 4 + 2] = k2; keys[i * 4 + 3] = k3;
        atomicAdd(&hist[k0 >> 21], 1u);
        atomicAdd(&hist[k1 >> 21], 1u);
        atomicAdd(&hist[k2 >> 21], 1u);
        atomicAdd(&hist[k3 >> 21], 1u);
    }
    __syncthreads();

    unsigned prefix = 0;
    unsigned need = TOPK;
    const int shifts[3]  = {21, 10, 0};
    const int bitsArr[3] = {11, 11, 10};

    for (int lvl = 0; lvl < 3; lvl++) {
        const int shift = shifts[lvl];
        const int bits = bitsArr[lvl];
        const int nb = 1 << bits;

        if (lvl > 0) {
            for (int i = tid; i < nb; i += 256) hist[i] = 0;
            __syncthreads();
            for (int it = 0; it < FEAT / 256; it++) {
                unsigned key = keys[tid + it * 256];
                if ((key >> (shift + bits)) == prefix)
                    atomicAdd(&hist[(key >> shift) & (nb - 1)], 1u);
            }
            __syncthreads();
        }

        // per-thread chunk sum
        const int stride = nb / 256;
        unsigned s = 0;
        #pragma unroll 4
        for (int j = 0; j < stride; j++) s += hist[tid * stride + j];
        tsum[tid] = s;
        __syncthreads();

        // reverse Hillis-Steele scan: tsum[t] -> suffix sum over [t..255]
        #pragma unroll
        for (int off = 1; off < 256; off <<= 1) {
            unsigned v = tsum[tid];
            unsigned add = (tid + off < 256) ? tsum[tid + off] : 0u;
            __syncthreads();
            tsum[tid] = v + add;
            __syncthreads();
        }
        unsigned suf = tsum[tid];           // count in buckets >= tid*stride
        // exactly one thread owns the chunk containing the K-th largest:
        // (count strictly above chunk) < need <= (count including chunk)
        if (suf >= need && (suf - s) < need) {
            unsigned cum = suf - s;         // count above this chunk
            unsigned dig = 0, rem = need;
            for (int b = (tid + 1) * stride - 1; b >= tid * stride; b--) {
                unsigned h = hist[b];
                if (cum + h >= need) { dig = (unsigned)b; rem = need - cum; break; }
                cum += h;
            }
            sh_digit = dig;
            sh_need = rem;
        }
        __syncthreads();
        prefix = (prefix << bits) | sh_digit;
        need = sh_need;
        __syncthreads();
    }

    const unsigned T = prefix;              // exact key of K-th largest
    if (tid == 0) { cnt = 0; eqn = 0; }
    __syncthreads();

    for (int it = 0; it < FEAT / 256; it++) {
        int i = tid + it * 256;
        unsigned key = keys[i];
        if (key > T) {
            int s2 = atomicAdd(&cnt, 1);
            g_tidx[row * TOPK + s2] = i;
            g_tval[row * TOPK + s2] = key_to_float(key);
        } else if (key == T) {
            int e = atomicAdd(&eqn, 1);
            if (e < 256) eqbuf[e] = i;
        }
    }
    __syncthreads();

    if (tid == 0) {
        int ne = eqn; if (ne > 256) ne = 256;
        for (int a = 1; a < ne; a++) {
            int v = eqbuf[a]; int b = a - 1;
            while (b >= 0 && eqbuf[b] > v) { eqbuf[b + 1] = eqbuf[b]; b--; }
            eqbuf[b + 1] = v;
        }
        float tv = key_to_float(T);
        int base = cnt;
        for (int j = 0; j < (int)need; j++) {
            g_tidx[row * TOPK + base + j] = eqbuf[j];
            g_tval[row * TOPK + base + j] = tv;
        }
    }
}

// ---------------- kernel: sparse decode ---------------------------------------
__global__ void __launch_bounds__(256) decode_kernel(const float* __restrict__ b_dec,
                                                     float* __restrict__ out) {
    const int row = blockIdx.x;
    const int t = threadIdx.x;
    __shared__ int   sidx[TOPK];
    __shared__ float sval[TOPK];
    if (t < TOPK) {
        sidx[t] = g_tidx[row * TOPK + t];
        sval[t] = g_tval[row * TOPK + t];
    }
    __syncthreads();

    float a0 = b_dec[t];
    float a1 = b_dec[t + 256];
    float a2 = b_dec[t + 512];
    #pragma unroll 4
    for (int k = 0; k < TOPK; k++) {
        const float* w = g_WdT + (size_t)sidx[k] * DIM;
        float v = sval[k];
        a0 += v * w[t];
        a1 += v * w[t + 256];
        a2 += v * w[t + 512];
    }
    float* o = out + (size_t)row * DIM;
    o[t] = a0;
    o[t + 256] = a1;
    o[t + 512] = a2;
}

// ---------------- launcher -----------------------------------------------------
extern "C" void kernel_launch(void* const* d_in, const int* in_sizes, int n_in,
                              void* d_out, int out_size) {
    const float* x     = (const float*)d_in[0];
    const float* W_enc = (const float*)d_in[1];
    const float* b_enc = (const float*)d_in[2];
    const float* W_dec = (const float*)d_in[3];
    const float* b_dec = (const float*)d_in[4];
    float* out = (float*)d_out;

    cudaFuncSetAttribute(encode_gemm_kernel,
                         cudaFuncAttributeMaxDynamicSharedMemorySize, SMEM_BYTES);
    cudaFuncSetAttribute(topk_kernel,
                         cudaFuncAttributeMaxDynamicSharedMemorySize, TK_SMEM_BYTES);

    split_xw_kernel<<<(int)(((size_t)FEAT * DIM + 255) / 256), 256>>>(x, b_dec, W_enc);

    dim3 tgrid(FEAT / 32, DIM / 32);
    dim3 tblk(32, 8);
    transpose_wdec_kernel<<<tgrid, tblk>>>(W_dec);

    dim3 ggrid(BATCH / BM, FEAT / BN);   // x = M tiles, y = N tiles
    encode_gemm_kernel<<<ggrid, GTHREADS, SMEM_BYTES>>>(b_enc);

    topk_kernel<<<BATCH, 256, TK_SMEM_BYTES>>>();

    decode_kernel<<<BATCH, 256>>>(b_dec, out);
}